// round 11
// baseline (speedup 1.0000x reference)
#include <cuda_runtime.h>

#define NTREE 64
#define NPT   3280
#define NINT  1093
#define CD    8
#define GD    8
#define MS    128
#define TPB   256

typedef unsigned long long u64;

// smem layout (floats). Beta: stride-8 nodes with intra-node half-swap swizzle.
#define OFF_S     (NINT*8)               // 8744
#define OFF_BM    (OFF_S + 1096)
#define OFF_ASP   (OFF_BM + MS*CD)
#define OFF_A2    (OFF_ASP + 3*CD*CD)
#define OFF_PI    (OFF_A2  + 3*CD*CD)
#define OFF_LPI   (OFF_PI  + 3*CD)
#define OFF_RED   (OFF_LPI + 3*CD)
#define SMEM_FLOATS (OFF_RED + 8)
#define SMEM_BYTES  (SMEM_FLOATS * 4)    // ~45.2 KB -> 4 CTAs/SM

// ---------- f32x2 packed helpers (FFMA2 only reachable via PTX) ----------
__device__ __forceinline__ u64 pk2(float lo, float hi) {
    u64 r; asm("mov.b64 %0, {%1,%2};" : "=l"(r) : "f"(lo), "f"(hi)); return r;
}
__device__ __forceinline__ void upk2(u64 v, float& lo, float& hi) {
    asm("mov.b64 {%0,%1}, %2;" : "=f"(lo), "=f"(hi) : "l"(v));
}
__device__ __forceinline__ u64 ffma2(u64 a, u64 b, u64 c) {
    u64 d; asm("fma.rn.f32x2 %0, %1, %2, %3;" : "=l"(d) : "l"(a), "l"(b), "l"(c)); return d;
}
// load 8 floats as 4 packed f32x2 (16B-aligned)
__device__ __forceinline__ void ld8p(const float* p, u64* v) {
    ulonglong2 a = *reinterpret_cast<const ulonglong2*>(p);
    ulonglong2 b = *reinterpret_cast<const ulonglong2*>(p + 4);
    v[0]=a.x; v[1]=a.y; v[2]=b.x; v[3]=b.y;
}
__device__ __forceinline__ float dot8p(const u64* a, const u64* w) {
    u64 acc = ffma2(a[0], w[0], 0ull);
    acc = ffma2(a[1], w[1], acc);
    acc = ffma2(a[2], w[2], acc);
    acc = ffma2(a[3], w[3], acc);
    float lo, hi; upk2(acc, lo, hi);
    return lo + hi;
}

__device__ __forceinline__ int get_x(const void* xr, bool is64, size_t idx) {
    return is64 ? (int)((const long long*)xr)[idx] : ((const int*)xr)[idx];
}
__device__ __forceinline__ void ld8(const float* p, float* v) {
    float4 a = reinterpret_cast<const float4*>(p)[0];
    float4 b = reinterpret_cast<const float4*>(p)[1];
    v[0]=a.x; v[1]=a.y; v[2]=a.z; v[3]=a.w; v[4]=b.x; v[5]=b.y; v[6]=b.z; v[7]=b.w;
}
// swizzled beta access: node n, halves swapped when n&4. No overlap; conflict-free
// for stride-1 and stride-3 node lane patterns.
__device__ __forceinline__ void ld8s(const float* base, int n, float* v) {
    int o = n & 4;
    float4 a = *reinterpret_cast<const float4*>(base + 8*n + o);
    float4 b = *reinterpret_cast<const float4*>(base + 8*n + (o^4));
    v[0]=a.x; v[1]=a.y; v[2]=a.z; v[3]=a.w; v[4]=b.x; v[5]=b.y; v[6]=b.z; v[7]=b.w;
}
// same, but returning packed f32x2 pairs
__device__ __forceinline__ void ld8sp(const float* base, int n, u64* v) {
    int o = n & 4;
    ulonglong2 a = *reinterpret_cast<const ulonglong2*>(base + 8*n + o);
    ulonglong2 b = *reinterpret_cast<const ulonglong2*>(base + 8*n + (o^4));
    v[0]=a.x; v[1]=a.y; v[2]=b.x; v[3]=b.y;
}
__device__ __forceinline__ void st8s(float* base, int n, const float* v) {
    int o = n & 4;
    *reinterpret_cast<float4*>(base + 8*n + o)     = make_float4(v[0],v[1],v[2],v[3]);
    *reinterpret_cast<float4*>(base + 8*n + (o^4)) = make_float4(v[4],v[5],v[6],v[7]);
}

__global__ __launch_bounds__(TPB, 4)
void phtmm_kernel(const float* __restrict__ lamA, const float* __restrict__ lamB,
                  const float* __restrict__ lamPi, const float* __restrict__ lamSP,
                  const void* __restrict__ xraw, float* __restrict__ out)
{
    extern __shared__ __align__(16) float sm[];
    float* sBeta = sm;                 // beta [swizzled]; overwritten by w downward
    float* sS    = sm + OFF_S;         // per-node normalizer S
    float* sBm   = sm + OFF_BM;        // softmax(B)[m][c]
    float* sASP  = sm + OFF_ASP;       // SP*A        [b][cp][c]
    float* sA2   = sm + OFF_A2;        // SP*A*logA
    float* sPi   = sm + OFF_PI;
    float* sLPi  = sm + OFF_LPI;
    float* sRed  = sm + OFF_RED;

    const int tid  = threadIdx.x;
    const int g    = blockIdx.x;
    const int t    = blockIdx.y;
    const int lane = tid & 31;
    const int wid  = tid >> 5;

    bool is64;
    {
        const long long* p = (const long long*)xraw;
        long long m = p[0]|p[1]|p[2]|p[3]|p[4]|p[5]|p[6]|p[7];
        is64 = ((unsigned long long)m < (unsigned long long)MS);
    }

    // ---- SP log-softmax (registers) ----
    float lsp[3];
    {
        float v0 = lamSP[g], v1 = lamSP[GD+g], v2 = lamSP[2*GD+g];
        float mx = fmaxf(v0, fmaxf(v1, v2));
        float e0 = __expf(v0-mx), e1 = __expf(v1-mx), e2 = __expf(v2-mx);
        float ld = __logf(e0+e1+e2);
        lsp[0] = (v0-mx)-ld; lsp[1] = (v1-mx)-ld; lsp[2] = (v2-mx)-ld;
    }

    // ---- B softmax: 8 warps; warp w -> column c = w, lanes over m ----
    {
        const int c = wid;
        const float* bb = lamB + (size_t)c * MS * GD + g;
        float v[4]; float mx = -1e30f;
        #pragma unroll
        for (int j = 0; j < 4; j++) { v[j] = bb[(size_t)(lane + 32*j)*GD]; mx = fmaxf(mx, v[j]); }
        #pragma unroll
        for (int o = 16; o >= 1; o >>= 1) mx = fmaxf(mx, __shfl_xor_sync(0xffffffffu, mx, o));
        float e[4]; float den = 0.f;
        #pragma unroll
        for (int j = 0; j < 4; j++) { e[j] = __expf(v[j]-mx); den += e[j]; }
        #pragma unroll
        for (int o = 16; o >= 1; o >>= 1) den += __shfl_xor_sync(0xffffffffu, den, o);
        float inv = __fdividef(1.f, den);
        #pragma unroll
        for (int j = 0; j < 4; j++) sBm[(lane + 32*j)*CD + c] = e[j]*inv;
    }

    // ---- A softmax over c (fold SP), Pi softmax ----
    if (tid < 24) {
        int b = tid % 3, cp = tid / 3;
        float sp = __expf(lsp[b]);
        float a[CD]; float mx = -1e30f;
        #pragma unroll
        for (int c = 0; c < CD; c++) { a[c] = lamA[((c*CD+cp)*3+b)*GD + g]; mx = fmaxf(mx, a[c]); }
        float den = 0.f;
        #pragma unroll
        for (int c = 0; c < CD; c++) den += __expf(a[c]-mx);
        float ld = __logf(den), inv = __fdividef(1.f, den);
        #pragma unroll
        for (int c = 0; c < CD; c++) {
            float soft = __expf(a[c]-mx) * inv;
            float lg   = (a[c]-mx) - ld;
            sASP[(b*CD+cp)*CD + c] = sp * soft;
            sA2 [(b*CD+cp)*CD + c] = sp * soft * lg;
        }
    } else if (tid < 27) {
        int b = tid - 24;
        float a[CD]; float mx = -1e30f;
        #pragma unroll
        for (int c = 0; c < CD; c++) { a[c] = lamPi[(c*3+b)*GD + g]; mx = fmaxf(mx, a[c]); }
        float den = 0.f;
        #pragma unroll
        for (int c = 0; c < CD; c++) den += __expf(a[c]-mx);
        float ld = __logf(den), inv = __fdividef(1.f, den);
        #pragma unroll
        for (int c = 0; c < CD; c++) {
            sPi [b*CD + c] = __expf(a[c]-mx) * inv;
            sLPi[b*CD + c] = (a[c]-mx) - ld;
        }
    }
    __syncthreads();

    const size_t xoff = (size_t)t * NPT;

    // finish a parent: packed acc2 = t_beta -> S, normalized beta
    auto finish = [&](int p, u64* acc2) {
        float acc[CD];
        upk2(acc2[0], acc[0], acc[1]);
        upk2(acc2[1], acc[2], acc[3]);
        upk2(acc2[2], acc[4], acc[5]);
        upk2(acc2[3], acc[6], acc[7]);
        int xv = get_x(xraw, is64, xoff + p);
        float bm[CD]; ld8(sBm + xv*CD, bm);
        float s = 0.f;
        #pragma unroll
        for (int c = 0; c < CD; c++) { acc[c] *= bm[c]; s += acc[c]; }
        sS[p] = s;
        float inv = __fdividef(1.f, s);
        #pragma unroll
        for (int c = 0; c < CD; c++) acc[c] *= inv;
        st8s(sBeta, p, acc);
    };

    // ===== upward level 7 (leaf children recomputed on the fly) =====
    for (int p = 364 + tid; p < 1093; p += TPB) {
        u64 acc2[4] = {0ull,0ull,0ull,0ull};
        int cb = 1093 + 3*(p - 364);
        #pragma unroll
        for (int b = 0; b < 3; b++) {
            int xv = get_x(xraw, is64, xoff + cb + b);
            float v[CD]; ld8(sBm + xv*CD, v);
            float s = 0.f;
            #pragma unroll
            for (int c = 0; c < CD; c++) { v[c] *= sPi[b*CD+c]; s += v[c]; }
            float inv = __fdividef(1.f, s);
            #pragma unroll
            for (int cp = 0; cp < CD; cp++) {
                u64 av[4]; ld8p(sASP + (b*CD+cp)*CD, av);
                float vv = v[cp]*inv;
                u64 xx = pk2(vv, vv);
                acc2[0] = ffma2(av[0], xx, acc2[0]);
                acc2[1] = ffma2(av[1], xx, acc2[1]);
                acc2[2] = ffma2(av[2], xx, acc2[2]);
                acc2[3] = ffma2(av[3], xx, acc2[3]);
            }
        }
        finish(p, acc2);
    }
    __syncthreads();

    // ===== upward levels 6..1 =====
    {
        int p0 = 121, p1 = 364;
        #pragma unroll 1
        for (int d = 6; d >= 1; --d) {
            for (int p = p0 + tid; p < p1; p += TPB) {
                u64 acc2[4] = {0ull,0ull,0ull,0ull};
                int cb = p1 + 3*(p - p0);
                #pragma unroll
                for (int b = 0; b < 3; b++) {
                    float bc[CD]; ld8s(sBeta, cb+b, bc);
                    #pragma unroll
                    for (int cp = 0; cp < CD; cp++) {
                        u64 av[4]; ld8p(sASP + (b*CD+cp)*CD, av);
                        u64 xx = pk2(bc[cp], bc[cp]);
                        acc2[0] = ffma2(av[0], xx, acc2[0]);
                        acc2[1] = ffma2(av[1], xx, acc2[1]);
                        acc2[2] = ffma2(av[2], xx, acc2[2]);
                        acc2[3] = ffma2(av[3], xx, acc2[3]);
                    }
                }
                finish(p, acc2);
            }
            p1 = p0; p0 = (p0 - 1) / 3;
            __syncthreads();
        }
    }

    // ===== downward: root =====
    float ell = 0.f;
    if (tid == 0) {
        int xv = get_x(xraw, is64, xoff);
        float bm[CD]; ld8(sBm + xv*CD, bm);
        float bv[CD]; ld8s(sBeta, 0, bv);
        float invS = __fdividef(1.f, sS[0]);
        float w[CD];
        #pragma unroll
        for (int c = 0; c < CD; c++) {
            ell = fmaf(bv[c], bm[c], ell);
            w[c] = bm[c] * invS;            // w = beta/t_beta = bm/S
        }
        st8s(sBeta, 0, w);
    }
    __syncthreads();

    // ===== downward levels 1..6 (children internal), two-pass inner loop =====
    {
        int p0 = 0, p1 = 1;
        #pragma unroll 1
        for (int d = 1; d <= 6; ++d) {
            for (int p = p0 + tid; p < p1; p += TPB) {
                u64 wp[4]; ld8sp(sBeta, p, wp);          // parent w, packed
                int cb = p1 + 3*(p - p0);
                #pragma unroll
                for (int b = 0; b < 3; b++) {
                    int ch = cb + b;
                    float bc[CD]; ld8s(sBeta, ch, bc);
                    // pass A: A2 dots (needs only wp, bc)
                    float s2 = 0.f;
                    #pragma unroll
                    for (int cp = 0; cp < CD; cp++) {
                        u64 a2[4]; ld8p(sA2 + (b*CD+cp)*CD, a2);
                        s2 = fmaf(bc[cp], dot8p(a2, wp), s2);
                    }
                    // pass B: ASP dots -> e, se, ebm, wv
                    int xv = get_x(xraw, is64, xoff + ch);
                    float bm[CD]; ld8(sBm + xv*CD, bm);
                    float invS = __fdividef(1.f, sS[ch]);
                    float wv[CD]; float se = 0.f, ebm = 0.f;
                    #pragma unroll
                    for (int cp = 0; cp < CD; cp++) {
                        u64 av[4]; ld8p(sASP + (b*CD+cp)*CD, av);
                        float t1 = dot8p(av, wp);
                        float e  = bc[cp]*t1;
                        se  += e;
                        ebm  = fmaf(e, bm[cp], ebm);
                        wv[cp] = t1 * bm[cp] * invS;     // w_ch = t1*bm/S
                    }
                    ell += s2 + se*lsp[b] + ebm;
                    st8s(sBeta, ch, wv);                 // overwrite child beta with w
                }
            }
            p0 = p1; p1 = 3*p1 + 1;
            __syncthreads();
        }
    }

    // ===== downward level 7 (leaf children; beta recomputed, + logPi) =====
    for (int p = 364 + tid; p < 1093; p += TPB) {
        u64 wp[4]; ld8sp(sBeta, p, wp);
        int cb = 1093 + 3*(p - 364);
        #pragma unroll
        for (int b = 0; b < 3; b++) {
            int ch = cb + b;
            int xv = get_x(xraw, is64, xoff + ch);
            float bm[CD]; ld8(sBm + xv*CD, bm);
            float bc[CD]; float s = 0.f;
            #pragma unroll
            for (int c = 0; c < CD; c++) { bc[c] = sPi[b*CD+c]*bm[c]; s += bc[c]; }
            float inv = __fdividef(1.f, s);
            #pragma unroll
            for (int c = 0; c < CD; c++) bc[c] *= inv;
            // pass A: A2 dots
            float s2 = 0.f;
            #pragma unroll
            for (int cp = 0; cp < CD; cp++) {
                u64 a2[4]; ld8p(sA2 + (b*CD+cp)*CD, a2);
                s2 = fmaf(bc[cp], dot8p(a2, wp), s2);
            }
            // pass B: ASP dots
            float lpv[CD]; ld8(sLPi + b*CD, lpv);
            float se = 0.f, ebm = 0.f, elp = 0.f;
            #pragma unroll
            for (int cp = 0; cp < CD; cp++) {
                u64 av[4]; ld8p(sASP + (b*CD+cp)*CD, av);
                float t1 = dot8p(av, wp);
                float e  = bc[cp]*t1;
                se  += e;
                ebm  = fmaf(e, bm[cp], ebm);
                elp  = fmaf(e, lpv[cp], elp);
            }
            ell += s2 + se*lsp[b] + ebm + elp;
        }
    }

    // ===== reduce + write =====
    #pragma unroll
    for (int o = 16; o >= 1; o >>= 1) ell += __shfl_down_sync(0xffffffffu, ell, o);
    if (lane == 0) sRed[wid] = ell;
    __syncthreads();
    if (tid == 0) {
        float s = 0.f;
        #pragma unroll
        for (int wI = 0; wI < 8; wI++) s += sRed[wI];
        out[t*GD + g] = -s;
    }
}

extern "C" void kernel_launch(void* const* d_in, const int* in_sizes, int n_in,
                              void* d_out, int out_size) {
    // inputs: 0 lam_A, 1 lam_B, 2 lam_Pi, 3 lam_SP, 4 x, 5 pos, 6 leaves, 7 batch
    cudaFuncSetAttribute(phtmm_kernel, cudaFuncAttributeMaxDynamicSharedMemorySize, SMEM_BYTES);
    dim3 grid(GD, NTREE);   // (g, tree) = 512 CTAs, single wave at 4 CTAs/SM
    phtmm_kernel<<<grid, TPB, SMEM_BYTES>>>((const float*)d_in[0], (const float*)d_in[1],
                                            (const float*)d_in[2], (const float*)d_in[3],
                                            d_in[4], (float*)d_out);
}

// round 13
// speedup vs baseline: 1.7971x; 1.7971x over previous
#include <cuda_runtime.h>

#define NTREE 64
#define NPT   3280
#define NINT  1093
#define CD    8
#define GD    8
#define MS    128
#define TPB   256

// Precomputed softmax(B): [g][m][c], 32B row per (g,m). Written by precompute
// kernel, gathered via LDG (32B-sector granularity beats LDS 128B lines for
// random row gathers).
__device__ float gBm[GD * MS * CD];

// smem layout (floats). Beta: stride-8 nodes with intra-node half-swap swizzle.
#define OFF_S     (NINT*8)               // 8744
#define OFF_ASP   (OFF_S + 1096)
#define OFF_A2    (OFF_ASP + 3*CD*CD)
#define OFF_PI    (OFF_A2  + 3*CD*CD)
#define OFF_LPI   (OFF_PI  + 3*CD)
#define OFF_RED   (OFF_LPI + 3*CD)
#define SMEM_FLOATS (OFF_RED + 8)
#define SMEM_BYTES  (SMEM_FLOATS * 4)    // ~41.1 KB -> 4 CTAs/SM

__device__ __forceinline__ int get_x(const void* xr, bool is64, size_t idx) {
    return is64 ? (int)((const long long*)xr)[idx] : ((const int*)xr)[idx];
}
__device__ __forceinline__ void ld8(const float* p, float* v) {
    float4 a = reinterpret_cast<const float4*>(p)[0];
    float4 b = reinterpret_cast<const float4*>(p)[1];
    v[0]=a.x; v[1]=a.y; v[2]=a.z; v[3]=a.w; v[4]=b.x; v[5]=b.y; v[6]=b.z; v[7]=b.w;
}
// global gather of a 32B Bm row (2 sectors via LDG.128)
__device__ __forceinline__ void ld8g(const float* p, float* v) {
    float4 a = __ldg(reinterpret_cast<const float4*>(p));
    float4 b = __ldg(reinterpret_cast<const float4*>(p) + 1);
    v[0]=a.x; v[1]=a.y; v[2]=a.z; v[3]=a.w; v[4]=b.x; v[5]=b.y; v[6]=b.z; v[7]=b.w;
}
// swizzled beta access: node n, halves swapped when n&4. No overlap; conflict-free
// for stride-1 and stride-3 node lane patterns.
__device__ __forceinline__ void ld8s(const float* base, int n, float* v) {
    int o = n & 4;
    float4 a = *reinterpret_cast<const float4*>(base + 8*n + o);
    float4 b = *reinterpret_cast<const float4*>(base + 8*n + (o^4));
    v[0]=a.x; v[1]=a.y; v[2]=a.z; v[3]=a.w; v[4]=b.x; v[5]=b.y; v[6]=b.z; v[7]=b.w;
}
__device__ __forceinline__ void st8s(float* base, int n, const float* v) {
    int o = n & 4;
    *reinterpret_cast<float4*>(base + 8*n + o)     = make_float4(v[0],v[1],v[2],v[3]);
    *reinterpret_cast<float4*>(base + 8*n + (o^4)) = make_float4(v[4],v[5],v[6],v[7]);
}
__device__ __forceinline__ float dot8(const float* a, const float* w) {
    float s = a[0]*w[0];
    #pragma unroll
    for (int c = 1; c < CD; c++) s = fmaf(a[c], w[c], s);
    return s;
}

// ===== precompute kernel: softmax(B) over m for all (g,c) into gBm =====
__global__ __launch_bounds__(256)
void precompute_bm_kernel(const float* __restrict__ lamB)
{
    const int lane = threadIdx.x & 31;
    const int wid  = threadIdx.x >> 5;
    for (int pair = wid; pair < GD*CD; pair += 8) {   // pair = c*GD + g
        int g = pair & 7, c = pair >> 3;
        const float* bb = lamB + (size_t)c * MS * GD + g;
        float v[4]; float mx = -1e30f;
        #pragma unroll
        for (int j = 0; j < 4; j++) { v[j] = bb[(size_t)(lane + 32*j)*GD]; mx = fmaxf(mx, v[j]); }
        #pragma unroll
        for (int o = 16; o >= 1; o >>= 1) mx = fmaxf(mx, __shfl_xor_sync(0xffffffffu, mx, o));
        float e[4]; float den = 0.f;
        #pragma unroll
        for (int j = 0; j < 4; j++) { e[j] = __expf(v[j]-mx); den += e[j]; }
        #pragma unroll
        for (int o = 16; o >= 1; o >>= 1) den += __shfl_xor_sync(0xffffffffu, den, o);
        float inv = __fdividef(1.f, den);
        #pragma unroll
        for (int j = 0; j < 4; j++)
            gBm[((size_t)g*MS + lane + 32*j)*CD + c] = e[j]*inv;
    }
}

__global__ __launch_bounds__(TPB, 4)
void phtmm_kernel(const float* __restrict__ lamA, const float* __restrict__ lamB,
                  const float* __restrict__ lamPi, const float* __restrict__ lamSP,
                  const void* __restrict__ xraw, float* __restrict__ out)
{
    extern __shared__ __align__(16) float sm[];
    float* sBeta = sm;                 // beta [swizzled]; overwritten by w downward
    float* sS    = sm + OFF_S;         // per-node normalizer S
    float* sASP  = sm + OFF_ASP;       // SP*A        [b][cp][c]
    float* sA2   = sm + OFF_A2;        // SP*A*logA
    float* sPi   = sm + OFF_PI;
    float* sLPi  = sm + OFF_LPI;
    float* sRed  = sm + OFF_RED;

    const int tid  = threadIdx.x;
    const int g    = blockIdx.x;
    const int t    = blockIdx.y;
    const int lane = tid & 31;
    const int wid  = tid >> 5;

    const float* bmg = gBm + (size_t)g * MS * CD;   // this CTA's Bm slice

    bool is64;
    {
        const long long* p = (const long long*)xraw;
        long long m = p[0]|p[1]|p[2]|p[3]|p[4]|p[5]|p[6]|p[7];
        is64 = ((unsigned long long)m < (unsigned long long)MS);
    }

    // ---- SP log-softmax (registers) ----
    float lsp[3];
    {
        float v0 = lamSP[g], v1 = lamSP[GD+g], v2 = lamSP[2*GD+g];
        float mx = fmaxf(v0, fmaxf(v1, v2));
        float e0 = __expf(v0-mx), e1 = __expf(v1-mx), e2 = __expf(v2-mx);
        float ld = __logf(e0+e1+e2);
        lsp[0] = (v0-mx)-ld; lsp[1] = (v1-mx)-ld; lsp[2] = (v2-mx)-ld;
    }

    // ---- A softmax over c (fold SP), Pi softmax ----
    if (tid < 24) {
        int b = tid % 3, cp = tid / 3;
        float sp = __expf(lsp[b]);
        float a[CD]; float mx = -1e30f;
        #pragma unroll
        for (int c = 0; c < CD; c++) { a[c] = lamA[((c*CD+cp)*3+b)*GD + g]; mx = fmaxf(mx, a[c]); }
        float den = 0.f;
        #pragma unroll
        for (int c = 0; c < CD; c++) den += __expf(a[c]-mx);
        float ld = __logf(den), inv = __fdividef(1.f, den);
        #pragma unroll
        for (int c = 0; c < CD; c++) {
            float soft = __expf(a[c]-mx) * inv;
            float lg   = (a[c]-mx) - ld;
            sASP[(b*CD+cp)*CD + c] = sp * soft;
            sA2 [(b*CD+cp)*CD + c] = sp * soft * lg;
        }
    } else if (tid < 27) {
        int b = tid - 24;
        float a[CD]; float mx = -1e30f;
        #pragma unroll
        for (int c = 0; c < CD; c++) { a[c] = lamPi[(c*3+b)*GD + g]; mx = fmaxf(mx, a[c]); }
        float den = 0.f;
        #pragma unroll
        for (int c = 0; c < CD; c++) den += __expf(a[c]-mx);
        float ld = __logf(den), inv = __fdividef(1.f, den);
        #pragma unroll
        for (int c = 0; c < CD; c++) {
            sPi [b*CD + c] = __expf(a[c]-mx) * inv;
            sLPi[b*CD + c] = (a[c]-mx) - ld;
        }
    }
    __syncthreads();

    const size_t xoff = (size_t)t * NPT;

    // finish a parent: acc = t_beta -> S, normalized beta
    auto finish = [&](int p, float* acc) {
        int xv = get_x(xraw, is64, xoff + p);
        float bm[CD]; ld8g(bmg + xv*CD, bm);
        float s = 0.f;
        #pragma unroll
        for (int c = 0; c < CD; c++) { acc[c] *= bm[c]; s += acc[c]; }
        sS[p] = s;
        float inv = __fdividef(1.f, s);
        #pragma unroll
        for (int c = 0; c < CD; c++) acc[c] *= inv;
        st8s(sBeta, p, acc);
    };

    // ===== upward level 7 (leaf children recomputed on the fly) =====
    for (int p = 364 + tid; p < 1093; p += TPB) {
        float acc[CD] = {0,0,0,0,0,0,0,0};
        int cb = 1093 + 3*(p - 364);
        #pragma unroll
        for (int b = 0; b < 3; b++) {
            int xv = get_x(xraw, is64, xoff + cb + b);
            float v[CD]; ld8g(bmg + xv*CD, v);
            float s = 0.f;
            #pragma unroll
            for (int c = 0; c < CD; c++) { v[c] *= sPi[b*CD+c]; s += v[c]; }
            float inv = __fdividef(1.f, s);
            #pragma unroll
            for (int cp = 0; cp < CD; cp++) {
                float av[CD]; ld8(sASP + (b*CD+cp)*CD, av);
                float bcv = v[cp]*inv;
                #pragma unroll
                for (int c = 0; c < CD; c++) acc[c] = fmaf(av[c], bcv, acc[c]);
            }
        }
        finish(p, acc);
    }
    __syncthreads();

    // ===== upward levels 6..1 =====
    {
        int p0 = 121, p1 = 364;
        #pragma unroll 1
        for (int d = 6; d >= 1; --d) {
            for (int p = p0 + tid; p < p1; p += TPB) {
                float acc[CD] = {0,0,0,0,0,0,0,0};
                int cb = p1 + 3*(p - p0);
                #pragma unroll
                for (int b = 0; b < 3; b++) {
                    float bc[CD]; ld8s(sBeta, cb+b, bc);
                    #pragma unroll
                    for (int cp = 0; cp < CD; cp++) {
                        float av[CD]; ld8(sASP + (b*CD+cp)*CD, av);
                        float bcv = bc[cp];
                        #pragma unroll
                        for (int c = 0; c < CD; c++) acc[c] = fmaf(av[c], bcv, acc[c]);
                    }
                }
                finish(p, acc);
            }
            p1 = p0; p0 = (p0 - 1) / 3;
            __syncthreads();
        }
    }

    // ===== downward: root =====
    float ell = 0.f;
    if (tid == 0) {
        int xv = get_x(xraw, is64, xoff);
        float bm[CD]; ld8g(bmg + xv*CD, bm);
        float bv[CD]; ld8s(sBeta, 0, bv);
        float invS = __fdividef(1.f, sS[0]);
        float w[CD];
        #pragma unroll
        for (int c = 0; c < CD; c++) {
            ell = fmaf(bv[c], bm[c], ell);
            w[c] = bm[c] * invS;            // w = beta/t_beta = bm/S
        }
        st8s(sBeta, 0, w);
    }
    __syncthreads();

    // ===== downward levels 1..6 (children internal), two-pass inner loop =====
    {
        int p0 = 0, p1 = 1;
        #pragma unroll 1
        for (int d = 1; d <= 6; ++d) {
            for (int p = p0 + tid; p < p1; p += TPB) {
                float w[CD]; ld8s(sBeta, p, w);          // parent w
                int cb = p1 + 3*(p - p0);
                #pragma unroll
                for (int b = 0; b < 3; b++) {
                    int ch = cb + b;
                    float bc[CD]; ld8s(sBeta, ch, bc);
                    // pass A: A2 dots (needs only w, bc)
                    float s2 = 0.f;
                    #pragma unroll
                    for (int cp = 0; cp < CD; cp++) {
                        float a2[CD]; ld8(sA2 + (b*CD+cp)*CD, a2);
                        s2 = fmaf(bc[cp], dot8(a2, w), s2);
                    }
                    // pass B: ASP dots -> e, se, ebm, wv
                    int xv = get_x(xraw, is64, xoff + ch);
                    float bm[CD]; ld8g(bmg + xv*CD, bm);
                    float invS = __fdividef(1.f, sS[ch]);
                    float wv[CD]; float se = 0.f, ebm = 0.f;
                    #pragma unroll
                    for (int cp = 0; cp < CD; cp++) {
                        float av[CD]; ld8(sASP + (b*CD+cp)*CD, av);
                        float t1 = dot8(av, w);
                        float e  = bc[cp]*t1;
                        se  += e;
                        ebm  = fmaf(e, bm[cp], ebm);
                        wv[cp] = t1 * bm[cp] * invS;     // w_ch = t1*bm/S
                    }
                    ell += s2 + se*lsp[b] + ebm;
                    st8s(sBeta, ch, wv);                 // overwrite child beta with w
                }
            }
            p0 = p1; p1 = 3*p1 + 1;
            __syncthreads();
        }
    }

    // ===== downward level 7 (leaf children; beta recomputed, + logPi) =====
    for (int p = 364 + tid; p < 1093; p += TPB) {
        float w[CD]; ld8s(sBeta, p, w);
        int cb = 1093 + 3*(p - 364);
        #pragma unroll
        for (int b = 0; b < 3; b++) {
            int ch = cb + b;
            int xv = get_x(xraw, is64, xoff + ch);
            float bm[CD]; ld8g(bmg + xv*CD, bm);
            float bc[CD]; float s = 0.f;
            #pragma unroll
            for (int c = 0; c < CD; c++) { bc[c] = sPi[b*CD+c]*bm[c]; s += bc[c]; }
            float inv = __fdividef(1.f, s);
            #pragma unroll
            for (int c = 0; c < CD; c++) bc[c] *= inv;
            // pass A: A2 dots
            float s2 = 0.f;
            #pragma unroll
            for (int cp = 0; cp < CD; cp++) {
                float a2[CD]; ld8(sA2 + (b*CD+cp)*CD, a2);
                s2 = fmaf(bc[cp], dot8(a2, w), s2);
            }
            // pass B: ASP dots
            float lpv[CD]; ld8(sLPi + b*CD, lpv);
            float se = 0.f, ebm = 0.f, elp = 0.f;
            #pragma unroll
            for (int cp = 0; cp < CD; cp++) {
                float av[CD]; ld8(sASP + (b*CD+cp)*CD, av);
                float t1 = dot8(av, w);
                float e  = bc[cp]*t1;
                se  += e;
                ebm  = fmaf(e, bm[cp], ebm);
                elp  = fmaf(e, lpv[cp], elp);
            }
            ell += s2 + se*lsp[b] + ebm + elp;
        }
    }

    // ===== reduce + write =====
    #pragma unroll
    for (int o = 16; o >= 1; o >>= 1) ell += __shfl_down_sync(0xffffffffu, ell, o);
    if (lane == 0) sRed[wid] = ell;
    __syncthreads();
    if (tid == 0) {
        float s = 0.f;
        #pragma unroll
        for (int wI = 0; wI < 8; wI++) s += sRed[wI];
        out[t*GD + g] = -s;
    }
}

extern "C" void kernel_launch(void* const* d_in, const int* in_sizes, int n_in,
                              void* d_out, int out_size) {
    // inputs: 0 lam_A, 1 lam_B, 2 lam_Pi, 3 lam_SP, 4 x, 5 pos, 6 leaves, 7 batch
    cudaFuncSetAttribute(phtmm_kernel, cudaFuncAttributeMaxDynamicSharedMemorySize, SMEM_BYTES);
    precompute_bm_kernel<<<1, 256>>>((const float*)d_in[1]);
    dim3 grid(GD, NTREE);   // (g, tree) = 512 CTAs, single wave at 4 CTAs/SM
    phtmm_kernel<<<grid, TPB, SMEM_BYTES>>>((const float*)d_in[0], (const float*)d_in[1],
                                            (const float*)d_in[2], (const float*)d_in[3],
                                            d_in[4], (float*)d_out);
}